// round 1
// baseline (speedup 1.0000x reference)
#include <cuda_runtime.h>
#include <math.h>
#include <stddef.h>

#define B_IMG 8192

// Intermediate activations (device globals: allocation-free rule)
__device__ float g_buf1[(size_t)B_IMG * 64 * 14 * 14];   // after stage1 pool
__device__ float g_buf2[(size_t)B_IMG * 128 * 7 * 7];    // after stage2 pool
__device__ float g_buf3[(size_t)B_IMG * 256 * 3 * 3];    // after stage3 pool

// ---------------------------------------------------------------------------
// Stage 1: conv1 (1->64, 3x3 SAME) + BN + ReLU + 2x2 maxpool  -> [B,64,14,14]
// One block per image.
// ---------------------------------------------------------------------------
__global__ __launch_bounds__(256) void conv1_kernel(
    const float* __restrict__ x, const float* __restrict__ w, const float* __restrict__ cb,
    const float* __restrict__ g, const float* __restrict__ bb,
    const float* __restrict__ m, const float* __restrict__ v)
{
    __shared__ float sIn[30 * 30];
    __shared__ float sW[64 * 9];
    __shared__ float sA[64];
    __shared__ float sB[64];
    int b = blockIdx.x, tid = threadIdx.x;

    for (int i = tid; i < 900; i += 256) sIn[i] = 0.f;
    for (int i = tid; i < 576; i += 256) sW[i] = w[i];
    if (tid < 64) {
        float a = g[tid] * rsqrtf(v[tid] + 1e-5f);
        sA[tid] = a;
        sB[tid] = (cb[tid] - m[tid]) * a + bb[tid];
    }
    __syncthreads();
    const float* xb = x + (size_t)b * 784;
    for (int i = tid; i < 784; i += 256) {
        int r = i / 28, c = i % 28;
        sIn[(r + 1) * 30 + c + 1] = xb[i];
    }
    __syncthreads();

    float* ob = g_buf1 + (size_t)b * 64 * 196;
    for (int idx = tid; idx < 64 * 196; idx += 256) {
        int oc = idx / 196, p = idx % 196;
        int py = p / 14, px = p % 14;
        const float* wp = sW + oc * 9;
        float w0 = wp[0], w1 = wp[1], w2 = wp[2], w3 = wp[3], w4 = wp[4],
              w5 = wp[5], w6 = wp[6], w7 = wp[7], w8 = wp[8];
        float alpha = sA[oc], beta = sB[oc];
        float best = -3.0e38f;
        #pragma unroll
        for (int dy = 0; dy < 2; dy++) {
            #pragma unroll
            for (int dx = 0; dx < 2; dx++) {
                const float* pi = sIn + (2 * py + dy) * 30 + 2 * px + dx;
                float acc = w0 * pi[0] + w1 * pi[1] + w2 * pi[2]
                          + w3 * pi[30] + w4 * pi[31] + w5 * pi[32]
                          + w6 * pi[60] + w7 * pi[61] + w8 * pi[62];
                best = fmaxf(best, alpha * acc + beta);
            }
        }
        ob[idx] = fmaxf(best, 0.f);
    }
}

// ---------------------------------------------------------------------------
// Stage 2: conv2 (64->128, 3x3 SAME on 14x14) + BN + ReLU + pool -> [B,128,7,7]
// Grid (B, 2): 64 output channels per block. 392 threads:
//   og = tid%8 (8 oc-groups, each owns ocs og, og+8, ..., og+56)
//   win = tid/8 (49 pooling windows of the 7x7 output)
// Register tile: 8 ocs x 4 conv pixels (the 2x2 pool window).
// ---------------------------------------------------------------------------
#define C2_THREADS 392
#define C2_SMEM ((64 * 256 + 64 * 145 + 128) * 4)

__global__ __launch_bounds__(392, 2) void conv2_kernel(
    const float* __restrict__ w, const float* __restrict__ cb,
    const float* __restrict__ g, const float* __restrict__ bb,
    const float* __restrict__ m, const float* __restrict__ v)
{
    extern __shared__ float sm2[];
    float* sIn = sm2;                   // 64 ch x 16x16 (padded), pitch 16
    float* sW  = sm2 + 64 * 256;        // 64 oc x (16 ic * 9 + 1 pad) = 64*145
    float* sA  = sW + 64 * 145;
    float* sB  = sA + 64;

    int b = blockIdx.x;
    int ocBase = blockIdx.y * 64;
    int tid = threadIdx.x;
    int og  = tid & 7;
    int win = tid >> 3;                 // 0..48
    int wy = win / 7, wx = win % 7;

    if (tid < 64) {
        int oc = ocBase + tid;
        float a = g[oc] * rsqrtf(v[oc] + 1e-5f);
        sA[tid] = a;
        sB[tid] = (cb[oc] - m[oc]) * a + bb[oc];
    }
    for (int i = tid; i < 64 * 256; i += C2_THREADS) sIn[i] = 0.f;
    __syncthreads();
    const float* ib = g_buf1 + (size_t)b * 64 * 196;
    for (int i = tid; i < 64 * 196; i += C2_THREADS) {
        int ic = i / 196, p = i % 196;
        int r = p / 14, c = p % 14;
        sIn[ic * 256 + (r + 1) * 16 + c + 1] = ib[i];
    }

    float acc[8][4];
    #pragma unroll
    for (int t = 0; t < 8; t++)
        #pragma unroll
        for (int j = 0; j < 4; j++) acc[t][j] = 0.f;

    for (int icc = 0; icc < 4; icc++) {
        __syncthreads();
        // load weight chunk: 64 oc x 16 ic x 9
        for (int i = tid; i < 64 * 16 * 9; i += C2_THREADS) {
            int ocl = i / 144;
            int rem = i - ocl * 144;
            int icl = rem / 9;
            int k = rem - icl * 9;
            sW[ocl * 145 + icl * 9 + k] =
                w[((size_t)(ocBase + ocl) * 64 + icc * 16 + icl) * 9 + k];
        }
        __syncthreads();
        #pragma unroll 1
        for (int ic = 0; ic < 16; ic++) {
            const float* pi = sIn + (icc * 16 + ic) * 256 + (2 * wy) * 16 + 2 * wx;
            float r0[4], r1[4], r2[4], r3[4];
            #pragma unroll
            for (int j = 0; j < 4; j++) {
                r0[j] = pi[j]; r1[j] = pi[16 + j]; r2[j] = pi[32 + j]; r3[j] = pi[48 + j];
            }
            #pragma unroll
            for (int t = 0; t < 8; t++) {
                const float* pw = sW + (og + 8 * t) * 145 + ic * 9;
                float w0 = pw[0], w1 = pw[1], w2 = pw[2], w3 = pw[3], w4 = pw[4],
                      w5 = pw[5], w6 = pw[6], w7 = pw[7], w8 = pw[8];
                acc[t][0] += w0*r0[0]+w1*r0[1]+w2*r0[2]+w3*r1[0]+w4*r1[1]+w5*r1[2]+w6*r2[0]+w7*r2[1]+w8*r2[2];
                acc[t][1] += w0*r0[1]+w1*r0[2]+w2*r0[3]+w3*r1[1]+w4*r1[2]+w5*r1[3]+w6*r2[1]+w7*r2[2]+w8*r2[3];
                acc[t][2] += w0*r1[0]+w1*r1[1]+w2*r1[2]+w3*r2[0]+w4*r2[1]+w5*r2[2]+w6*r3[0]+w7*r3[1]+w8*r3[2];
                acc[t][3] += w0*r1[1]+w1*r1[2]+w2*r1[3]+w3*r2[1]+w4*r2[2]+w5*r2[3]+w6*r3[1]+w7*r3[2]+w8*r3[3];
            }
        }
    }

    float* ob = g_buf2 + (size_t)b * 128 * 49;
    #pragma unroll
    for (int t = 0; t < 8; t++) {
        int ocl = og + 8 * t;
        float alpha = sA[ocl], beta = sB[ocl];
        float v0 = alpha * acc[t][0] + beta;
        float v1 = alpha * acc[t][1] + beta;
        float v2 = alpha * acc[t][2] + beta;
        float v3 = alpha * acc[t][3] + beta;
        float mm = fmaxf(fmaxf(v0, v1), fmaxf(v2, v3));
        ob[(ocBase + ocl) * 49 + win] = fmaxf(mm, 0.f);
    }
}

// ---------------------------------------------------------------------------
// Stage 3: conv3 (128->256 on 7x7) + BN + ReLU + pool -> [B,256,3,3]
// Only the 6x6 pre-pool region is computed (pool drops row/col 6).
// Grid (B, 2): 128 ocs per block. 144 threads: og = tid%16, win = tid/16 (9).
// ---------------------------------------------------------------------------
#define C3_THREADS 144
#define C3_SMEM ((128 * 81 + 128 * 73 + 256) * 4)

__global__ __launch_bounds__(144, 2) void conv3_kernel(
    const float* __restrict__ w, const float* __restrict__ cb,
    const float* __restrict__ g, const float* __restrict__ bb,
    const float* __restrict__ m, const float* __restrict__ v)
{
    extern __shared__ float sm3[];
    float* sIn = sm3;                   // 128 ch x 9x9 (padded), pitch 9
    float* sW  = sm3 + 128 * 81;        // 128 oc x (8 ic * 9 + 1 pad) = 128*73
    float* sA  = sW + 128 * 73;
    float* sB  = sA + 128;

    int b = blockIdx.x;
    int ocBase = blockIdx.y * 128;
    int tid = threadIdx.x;
    int og  = tid & 15;
    int win = tid >> 4;                 // 0..8
    int wy = win / 3, wx = win % 3;

    if (tid < 128) {
        int oc = ocBase + tid;
        float a = g[oc] * rsqrtf(v[oc] + 1e-5f);
        sA[tid] = a;
        sB[tid] = (cb[oc] - m[oc]) * a + bb[oc];
    }
    for (int i = tid; i < 128 * 81; i += C3_THREADS) sIn[i] = 0.f;
    __syncthreads();
    const float* ib = g_buf2 + (size_t)b * 128 * 49;
    for (int i = tid; i < 128 * 49; i += C3_THREADS) {
        int ic = i / 49, p = i % 49;
        int r = p / 7, c = p % 7;
        sIn[ic * 81 + (r + 1) * 9 + c + 1] = ib[i];
    }

    float acc[8][4];
    #pragma unroll
    for (int t = 0; t < 8; t++)
        #pragma unroll
        for (int j = 0; j < 4; j++) acc[t][j] = 0.f;

    for (int icc = 0; icc < 16; icc++) {
        __syncthreads();
        for (int i = tid; i < 128 * 8 * 9; i += C3_THREADS) {
            int ocl = i / 72;
            int rem = i - ocl * 72;
            int icl = rem / 9;
            int k = rem - icl * 9;
            sW[ocl * 73 + icl * 9 + k] =
                w[((size_t)(ocBase + ocl) * 128 + icc * 8 + icl) * 9 + k];
        }
        __syncthreads();
        #pragma unroll 1
        for (int ic = 0; ic < 8; ic++) {
            const float* pi = sIn + (icc * 8 + ic) * 81 + (2 * wy) * 9 + 2 * wx;
            float r0[4], r1[4], r2[4], r3[4];
            #pragma unroll
            for (int j = 0; j < 4; j++) {
                r0[j] = pi[j]; r1[j] = pi[9 + j]; r2[j] = pi[18 + j]; r3[j] = pi[27 + j];
            }
            #pragma unroll
            for (int t = 0; t < 8; t++) {
                const float* pw = sW + (og + 16 * t) * 73 + ic * 9;
                float w0 = pw[0], w1 = pw[1], w2 = pw[2], w3 = pw[3], w4 = pw[4],
                      w5 = pw[5], w6 = pw[6], w7 = pw[7], w8 = pw[8];
                acc[t][0] += w0*r0[0]+w1*r0[1]+w2*r0[2]+w3*r1[0]+w4*r1[1]+w5*r1[2]+w6*r2[0]+w7*r2[1]+w8*r2[2];
                acc[t][1] += w0*r0[1]+w1*r0[2]+w2*r0[3]+w3*r1[1]+w4*r1[2]+w5*r1[3]+w6*r2[1]+w7*r2[2]+w8*r2[3];
                acc[t][2] += w0*r1[0]+w1*r1[1]+w2*r1[2]+w3*r2[0]+w4*r2[1]+w5*r2[2]+w6*r3[0]+w7*r3[1]+w8*r3[2];
                acc[t][3] += w0*r1[1]+w1*r1[2]+w2*r1[3]+w3*r2[1]+w4*r2[2]+w5*r2[3]+w6*r3[1]+w7*r3[2]+w8*r3[3];
            }
        }
    }

    float* ob = g_buf3 + (size_t)b * 256 * 9;
    #pragma unroll
    for (int t = 0; t < 8; t++) {
        int ocl = og + 16 * t;
        float alpha = sA[ocl], beta = sB[ocl];
        float v0 = alpha * acc[t][0] + beta;
        float v1 = alpha * acc[t][1] + beta;
        float v2 = alpha * acc[t][2] + beta;
        float v3 = alpha * acc[t][3] + beta;
        float mm = fmaxf(fmaxf(v0, v1), fmaxf(v2, v3));
        ob[(ocBase + ocl) * 9 + win] = fmaxf(mm, 0.f);
    }
}

// ---------------------------------------------------------------------------
// Tail: s = flat(buf3) . fc1_w[1] + fc1_b[1];  q = cos(s)*cos(qp[1]);
//       logits_k = q*A_k + C_k;  log_softmax.
// One warp per image (8 images / block).
// ---------------------------------------------------------------------------
__global__ __launch_bounds__(256) void tail_kernel(
    const float* __restrict__ fc1_w, const float* __restrict__ fc1_b,
    const float* __restrict__ qp,
    const float* __restrict__ fc2_w, const float* __restrict__ fc2_b,
    const float* __restrict__ fc3_w, const float* __restrict__ fc3_b,
    float* __restrict__ out)
{
    __shared__ float sAC[4];
    int tid = threadIdx.x;
    if (tid == 0) {
        float a0 = 0.f, a1 = 0.f, c0 = 0.f, c1 = 0.f;
        for (int j = 0; j < 128; j++) {
            float f2 = fc2_w[j];
            float f2b = fc2_b[j];
            a0 += fc3_w[j] * f2;        a1 += fc3_w[128 + j] * f2;
            c0 += fc3_w[j] * f2b;       c1 += fc3_w[128 + j] * f2b;
        }
        sAC[0] = a0; sAC[1] = a1;
        sAC[2] = c0 + fc3_b[0]; sAC[3] = c1 + fc3_b[1];
    }
    __syncthreads();

    int warp = tid >> 5, lane = tid & 31;
    int b = blockIdx.x * 8 + warp;
    const float* p3 = g_buf3 + (size_t)b * 2304;
    const float* w1 = fc1_w + 2304;     // row 1 of fc1_w
    float s = 0.f;
    for (int i = lane; i < 2304; i += 32) s += p3[i] * w1[i];
    #pragma unroll
    for (int o = 16; o; o >>= 1) s += __shfl_xor_sync(0xffffffffu, s, o);
    if (lane == 0) {
        s += fc1_b[1];
        float q = cosf(s) * cosf(qp[1]);
        float l0 = q * sAC[0] + sAC[2];
        float l1 = q * sAC[1] + sAC[3];
        float mx = fmaxf(l0, l1);
        float lse = mx + logf(expf(l0 - mx) + expf(l1 - mx));
        out[(size_t)b * 2]     = l0 - lse;
        out[(size_t)b * 2 + 1] = l1 - lse;
    }
}

// ---------------------------------------------------------------------------
extern "C" void kernel_launch(void* const* d_in, const int* in_sizes, int n_in,
                              void* d_out, int out_size)
{
    const float* x    = (const float*)d_in[0];
    const float* c1w  = (const float*)d_in[1];
    const float* c1b  = (const float*)d_in[2];
    const float* c2w  = (const float*)d_in[3];
    const float* c2b  = (const float*)d_in[4];
    const float* c3w  = (const float*)d_in[5];
    const float* c3b  = (const float*)d_in[6];
    const float* bn1g = (const float*)d_in[7];
    const float* bn1b = (const float*)d_in[8];
    const float* bn1m = (const float*)d_in[9];
    const float* bn1v = (const float*)d_in[10];
    const float* bn2g = (const float*)d_in[11];
    const float* bn2b = (const float*)d_in[12];
    const float* bn2m = (const float*)d_in[13];
    const float* bn2v = (const float*)d_in[14];
    const float* bn3g = (const float*)d_in[15];
    const float* bn3b = (const float*)d_in[16];
    const float* bn3m = (const float*)d_in[17];
    const float* bn3v = (const float*)d_in[18];
    const float* fc1w = (const float*)d_in[19];
    const float* fc1b = (const float*)d_in[20];
    const float* qpar = (const float*)d_in[21];
    const float* fc2w = (const float*)d_in[22];
    const float* fc2b = (const float*)d_in[23];
    const float* fc3w = (const float*)d_in[24];
    const float* fc3b = (const float*)d_in[25];
    float* out = (float*)d_out;

    cudaFuncSetAttribute(conv2_kernel, cudaFuncAttributeMaxDynamicSharedMemorySize, C2_SMEM);
    cudaFuncSetAttribute(conv3_kernel, cudaFuncAttributeMaxDynamicSharedMemorySize, C3_SMEM);

    conv1_kernel<<<B_IMG, 256>>>(x, c1w, c1b, bn1g, bn1b, bn1m, bn1v);
    conv2_kernel<<<dim3(B_IMG, 2), C2_THREADS, C2_SMEM>>>(c2w, c2b, bn2g, bn2b, bn2m, bn2v);
    conv3_kernel<<<dim3(B_IMG, 2), C3_THREADS, C3_SMEM>>>(c3w, c3b, bn3g, bn3b, bn3m, bn3v);
    tail_kernel<<<B_IMG / 8, 256>>>(fc1w, fc1b, qpar, fc2w, fc2b, fc3w, fc3b, out);
}

// round 3
// speedup vs baseline: 5.5933x; 5.5933x over previous
#include <cuda_runtime.h>
#include <cuda_bf16.h>
#include <math.h>
#include <stddef.h>
#include <stdint.h>

#define B_IMG 8192
#define PLANE_ELEMS (((size_t)B_IMG * 64 + 64) * 64)

// Persistent device buffers (module-load zero-init; never-written pads stay 0)
__device__ __nv_bfloat16 g_act1[((size_t)B_IMG * 256 + 64) * 64]; // [B*16*16+pad][64]
__device__ __nv_bfloat16 g_act2[2 * PLANE_ELEMS];                 // 2 planes [B*8*8+pad][64]
__device__ float         g_buf3[(size_t)B_IMG * 2304];            // [B][256*3*3]
__device__ __nv_bfloat16 g_w2T[9 * 128 * 64];                     // [s][oc][ic]
__device__ __nv_bfloat16 g_w3T[18 * 256 * 64];                    // [s9*2+h][oc][ic_local]

__device__ __forceinline__ uint32_t smem_u32(const void* p) {
    uint32_t a;
    asm("{ .reg .u64 t; cvta.to.shared.u64 t, %1; cvt.u32.u64 %0, t; }" : "=r"(a) : "l"(p));
    return a;
}

#define LDSM_X4(R, addr) \
    asm volatile("ldmatrix.sync.aligned.m8n8.x4.shared.b16 {%0,%1,%2,%3}, [%4];" \
                 : "=r"((R)[0]), "=r"((R)[1]), "=r"((R)[2]), "=r"((R)[3]) : "r"(addr))

#define MMA16816(d, a, b0, b1) \
    asm volatile("mma.sync.aligned.m16n8k16.row.col.f32.bf16.bf16.f32 " \
                 "{%0,%1,%2,%3}, {%4,%5,%6,%7}, {%8,%9}, {%0,%1,%2,%3};" \
                 : "+f"((d)[0]), "+f"((d)[1]), "+f"((d)[2]), "+f"((d)[3]) \
                 : "r"((a)[0]), "r"((a)[1]), "r"((a)[2]), "r"((a)[3]), "r"(b0), "r"(b1))

// ---------------------------------------------------------------------------
// conv1 (FFMA): 1->64, 3x3 SAME, BN+ReLU+pool -> bf16 padded NHWC act1 (16x16)
// ---------------------------------------------------------------------------
__global__ __launch_bounds__(256) void conv1_kernel(
    const float* __restrict__ x, const float* __restrict__ w, const float* __restrict__ cb,
    const float* __restrict__ g, const float* __restrict__ bb,
    const float* __restrict__ m, const float* __restrict__ v)
{
    __shared__ float sIn[30 * 30];
    __shared__ float sW[64 * 9];
    __shared__ float sA[64];
    __shared__ float sB[64];
    int b = blockIdx.x, tid = threadIdx.x;

    for (int i = tid; i < 900; i += 256) sIn[i] = 0.f;
    for (int i = tid; i < 576; i += 256) sW[i] = w[i];
    if (tid < 64) {
        float a = g[tid] * rsqrtf(v[tid] + 1e-5f);
        sA[tid] = a;
        sB[tid] = (cb[tid] - m[tid]) * a + bb[tid];
    }
    __syncthreads();
    const float* xb = x + (size_t)b * 784;
    for (int i = tid; i < 784; i += 256) {
        int r = i / 28, c = i % 28;
        sIn[(r + 1) * 30 + c + 1] = xb[i];
    }
    __syncthreads();

    int oc = tid & 63;
    const float* wp = sW + oc * 9;
    float w0 = wp[0], w1 = wp[1], w2 = wp[2], w3 = wp[3], w4 = wp[4],
          w5 = wp[5], w6 = wp[6], w7 = wp[7], w8 = wp[8];
    float alpha = sA[oc], beta = sB[oc];
    __nv_bfloat16* ob = g_act1 + (size_t)b * 256 * 64;

    for (int idx = tid; idx < 256 * 64; idx += 256) {
        int pos = idx >> 6;
        int r = pos >> 4, c = pos & 15;
        float outv = 0.f;
        if (r >= 1 && r <= 14 && c >= 1 && c <= 14) {
            int py = r - 1, px = c - 1;
            float best = -3.0e38f;
            #pragma unroll
            for (int dy = 0; dy < 2; dy++)
                #pragma unroll
                for (int dx = 0; dx < 2; dx++) {
                    const float* pi = sIn + (2 * py + dy) * 30 + 2 * px + dx;
                    float acc = w0 * pi[0] + w1 * pi[1] + w2 * pi[2]
                              + w3 * pi[30] + w4 * pi[31] + w5 * pi[32]
                              + w6 * pi[60] + w7 * pi[61] + w8 * pi[62];
                    best = fmaxf(best, alpha * acc + beta);
                }
            outv = fmaxf(best, 0.f);
        }
        ob[idx] = __float2bfloat16(outv);
    }
}

// ---------------------------------------------------------------------------
// Weight transform: OIHW fp32 -> offset-major bf16 GEMM A-tiles
// ---------------------------------------------------------------------------
__global__ __launch_bounds__(256) void wtrans_kernel(
    const float* __restrict__ w2, const float* __restrict__ w3)
{
    int i = blockIdx.x * 256 + threadIdx.x;
    if (i < 9 * 128 * 64) {
        int ic = i & 63, t = i >> 6;
        int oc = t & 127, s = t >> 7;
        g_w2T[i] = __float2bfloat16(w2[(oc * 64 + ic) * 9 + s]);
    }
    if (i < 18 * 256 * 64) {
        int icl = i & 63, t = i >> 6;
        int oc = t & 255, gi = t >> 8;      // gi = s9*2 + h
        int h = gi & 1, s9 = gi >> 1;
        g_w3T[i] = __float2bfloat16(w3[(oc * 128 + h * 64 + icl) * 9 + s9]);
    }
}

// ---------------------------------------------------------------------------
// conv2 HMMA (persistent): D[128oc x 256pos] per image, 9 shifts x K=64.
// Smem: 9 weight tiles resident (144B pitch), one activation tile per image.
// Epilogue: BN+ReLU+2x2pool -> bf16 act2.
// ---------------------------------------------------------------------------
#define C2_SW_BYTES (9 * 128 * 144)              // 165888
#define C2_SB_OFF   C2_SW_BYTES
#define C2_SMEM     (C2_SW_BYTES + 264 * 144)    // 203904

__global__ __launch_bounds__(512, 1) void conv2_mma(
    const float* __restrict__ cb, const float* __restrict__ g,
    const float* __restrict__ bb, const float* __restrict__ m,
    const float* __restrict__ v)
{
    extern __shared__ char dsm[];
    uint32_t sb = smem_u32(dsm);
    int tid = threadIdx.x;
    int lane = tid & 31, warp = tid >> 5;
    int wm = warp & 3, wn = warp >> 2;
    int t4 = lane & 3, trow = lane >> 2;

    // Load all 9 weight tiles into pitched smem
    for (int i = tid; i < 9216; i += 512) {
        uint4 val = ((const uint4*)g_w2T)[i];
        *(uint4*)(dsm + (i >> 3) * 144 + (i & 7) * 16) = val;
    }

    // BN affine per thread's 4 oc rows
    float al[2][2], be[2][2];
    #pragma unroll
    for (int i = 0; i < 2; i++)
        #pragma unroll
        for (int ro = 0; ro < 2; ro++) {
            int oc = wm * 32 + i * 16 + trow + ro * 8;
            float a = g[oc] * rsqrtf(v[oc] + 1e-5f);
            al[i][ro] = a;
            be[i][ro] = (cb[oc] - m[oc]) * a + bb[oc];
        }

    int npairs = (wn == 3) ? 2 : 4;

    for (int img = blockIdx.x; img < B_IMG; img += gridDim.x) {
        __syncthreads();
        const uint4* src = (const uint4*)(g_act1 + (size_t)img * 256 * 64);
        for (int i = tid; i < 264 * 8; i += 512)
            *(uint4*)(dsm + C2_SB_OFF + (i >> 3) * 144 + (i & 7) * 16) = src[i];
        __syncthreads();

        float acc[2][8][4];
        #pragma unroll
        for (int i = 0; i < 2; i++)
            #pragma unroll
            for (int j = 0; j < 8; j++)
                #pragma unroll
                for (int k = 0; k < 4; k++) acc[i][j][k] = 0.f;

        #pragma unroll 1
        for (int s = 0; s < 9; s++) {
            int shift = (s / 3) * 16 + (s % 3);
            uint32_t aB = sb + s * 18432 + (wm * 32) * 144;
            uint32_t bB = sb + C2_SB_OFF + (shift + wn * 64) * 144;
            #pragma unroll
            for (int kt = 0; kt < 4; kt++) {
                uint32_t a[2][4];
                #pragma unroll
                for (int i = 0; i < 2; i++) {
                    uint32_t addr = aB + (i * 16 + (lane & 15)) * 144 + ((lane >> 4) & 1) * 16 + kt * 32;
                    LDSM_X4(a[i], addr);
                }
                #pragma unroll
                for (int jp = 0; jp < 4; jp++) {
                    if (jp < npairs) {
                        uint32_t r[4];
                        uint32_t addr = bB + (jp * 16 + ((lane & 16) >> 1) + (lane & 7)) * 144
                                        + kt * 32 + ((lane >> 3) & 1) * 16;
                        LDSM_X4(r, addr);
                        #pragma unroll
                        for (int i = 0; i < 2; i++) {
                            MMA16816(acc[i][2 * jp],     a[i], r[0], r[1]);
                            MMA16816(acc[i][2 * jp + 1], a[i], r[2], r[3]);
                        }
                    }
                }
            }
        }

        // Epilogue: BN + ReLU + 2x2 pool -> act2 interior
        #pragma unroll
        for (int i = 0; i < 2; i++)
            #pragma unroll
            for (int jj = 0; jj < 4; jj++) {
                int j = (jj < 2) ? jj : jj + 2;   // {0,1,4,5}
                int n0 = wn * 64 + j * 8 + 2 * t4;
                int p = n0 + 17;
                int r = p >> 4, c = p & 15;
                if ((r & 1) && r < 15 && (c & 1) && c < 15) {
                    #pragma unroll
                    for (int ro = 0; ro < 2; ro++) {
                        float a = al[i][ro], bt = be[i][ro];
                        float v0 = a * acc[i][j][2 * ro] + bt;
                        float v1 = a * acc[i][j][2 * ro + 1] + bt;
                        float v2 = a * acc[i][j + 2][2 * ro] + bt;
                        float v3 = a * acc[i][j + 2][2 * ro + 1] + bt;
                        float mx = fmaxf(fmaxf(fmaxf(v0, v1), fmaxf(v2, v3)), 0.f);
                        int oc = wm * 32 + i * 16 + trow + ro * 8;
                        int py = (r - 1) >> 1, px = (c - 1) >> 1;
                        g_act2[(size_t)(oc >> 6) * PLANE_ELEMS +
                               ((size_t)img * 64 + (py + 1) * 8 + px + 1) * 64 + (oc & 63)]
                            = __float2bfloat16(mx);
                    }
                }
            }
    }
}

// ---------------------------------------------------------------------------
// conv3 HMMA: per CTA 4 images x 128 oc, 18 steps (9 shifts x 2 ic-halves).
// B (both act2 planes) loaded once; A tiles double-buffered.
// Epilogue: BN+ReLU+pool(6x6->3x3) -> fp32 g_buf3.
// ---------------------------------------------------------------------------
#define C3_SB_BYTES (280 * 144)                   // 40320 per plane
#define C3_A_OFF    (2 * C3_SB_BYTES)             // 80640
#define C3_A_BYTES  (128 * 144)                   // 18432 per stage
#define C3_SMEM     (C3_A_OFF + 2 * C3_A_BYTES)   // 117504

__global__ __launch_bounds__(512, 1) void conv3_mma(
    const float* __restrict__ cb, const float* __restrict__ g,
    const float* __restrict__ bb, const float* __restrict__ m,
    const float* __restrict__ v)
{
    extern __shared__ char dsm[];
    uint32_t sb = smem_u32(dsm);
    int tid = threadIdx.x;
    int lane = tid & 31, warp = tid >> 5;
    int wm = warp & 3, wn = warp >> 2;
    int t4 = lane & 3, trow = lane >> 2;
    int grp = blockIdx.x, half = blockIdx.y;

    // Load both activation planes (280 rows each)
    {
        const uint4* p0 = (const uint4*)(g_act2 + (size_t)grp * 256 * 64);
        const uint4* p1 = (const uint4*)(g_act2 + PLANE_ELEMS + (size_t)grp * 256 * 64);
        for (int i = tid; i < 280 * 8; i += 512) {
            uint32_t d = (i >> 3) * 144 + (i & 7) * 16;
            *(uint4*)(dsm + d) = p0[i];
            *(uint4*)(dsm + C3_SB_BYTES + d) = p1[i];
        }
    }
    // Load A tile 0
    {
        const uint4* sA = (const uint4*)(g_w3T + ((size_t)0 * 256 + half * 128) * 64);
        for (int i = tid; i < 1024; i += 512)
            *(uint4*)(dsm + C3_A_OFF + (i >> 3) * 144 + (i & 7) * 16) = sA[i];
    }
    __syncthreads();

    float acc[2][8][4];
    #pragma unroll
    for (int i = 0; i < 2; i++)
        #pragma unroll
        for (int j = 0; j < 8; j++)
            #pragma unroll
            for (int k = 0; k < 4; k++) acc[i][j][k] = 0.f;

    #pragma unroll 1
    for (int s = 0; s < 18; s++) {
        if (s < 17) {   // prefetch next A tile into other stage
            const uint4* sA = (const uint4*)(g_w3T + ((size_t)(s + 1) * 256 + half * 128) * 64);
            uint32_t stg = C3_A_OFF + ((s + 1) & 1) * C3_A_BYTES;
            for (int i = tid; i < 1024; i += 512)
                *(uint4*)(dsm + stg + (i >> 3) * 144 + (i & 7) * 16) = sA[i];
        }
        int s9 = s >> 1, h = s & 1;
        int shift = (s9 / 3) * 8 + (s9 % 3);
        uint32_t aB = sb + C3_A_OFF + (s & 1) * C3_A_BYTES + (wm * 32) * 144;
        uint32_t bB = sb + h * C3_SB_BYTES + (shift + wn * 64) * 144;
        #pragma unroll
        for (int kt = 0; kt < 4; kt++) {
            uint32_t a[2][4];
            #pragma unroll
            for (int i = 0; i < 2; i++) {
                uint32_t addr = aB + (i * 16 + (lane & 15)) * 144 + ((lane >> 4) & 1) * 16 + kt * 32;
                LDSM_X4(a[i], addr);
            }
            #pragma unroll
            for (int jp = 0; jp < 4; jp++) {
                uint32_t r[4];
                uint32_t addr = bB + (jp * 16 + ((lane & 16) >> 1) + (lane & 7)) * 144
                                + kt * 32 + ((lane >> 3) & 1) * 16;
                LDSM_X4(r, addr);
                #pragma unroll
                for (int i = 0; i < 2; i++) {
                    MMA16816(acc[i][2 * jp],     a[i], r[0], r[1]);
                    MMA16816(acc[i][2 * jp + 1], a[i], r[2], r[3]);
                }
            }
        }
        __syncthreads();
    }

    // Epilogue: BN + ReLU + pool -> g_buf3. Warp n-col wn = local image.
    #pragma unroll
    for (int i = 0; i < 2; i++)
        #pragma unroll
        for (int jh = 0; jh < 3; jh++) {
            int j = 2 * jh;                 // {0,2,4}
            if (t4 < 3) {
                #pragma unroll
                for (int ro = 0; ro < 2; ro++) {
                    int ch = half * 128 + wm * 32 + i * 16 + trow + ro * 8;
                    float a = g[ch] * rsqrtf(v[ch] + 1e-5f);
                    float bt = (cb[ch] - m[ch]) * a + bb[ch];
                    float v0 = a * acc[i][j][2 * ro] + bt;
                    float v1 = a * acc[i][j][2 * ro + 1] + bt;
                    float v2 = a * acc[i][j + 1][2 * ro] + bt;
                    float v3 = a * acc[i][j + 1][2 * ro + 1] + bt;
                    float mx = fmaxf(fmaxf(fmaxf(v0, v1), fmaxf(v2, v3)), 0.f);
                    g_buf3[(size_t)(grp * 4 + wn) * 2304 + ch * 9 + jh * 3 + t4] = mx;
                }
            }
        }
}

// ---------------------------------------------------------------------------
// Tail: analytic quantum collapse + fc chain + log_softmax. 1 warp / image.
// ---------------------------------------------------------------------------
__global__ __launch_bounds__(256) void tail_kernel(
    const float* __restrict__ fc1_w, const float* __restrict__ fc1_b,
    const float* __restrict__ qp,
    const float* __restrict__ fc2_w, const float* __restrict__ fc2_b,
    const float* __restrict__ fc3_w, const float* __restrict__ fc3_b,
    float* __restrict__ out)
{
    __shared__ float sAC[4];
    int tid = threadIdx.x;
    if (tid == 0) {
        float a0 = 0.f, a1 = 0.f, c0 = 0.f, c1 = 0.f;
        for (int j = 0; j < 128; j++) {
            float f2 = fc2_w[j], f2b = fc2_b[j];
            a0 += fc3_w[j] * f2;       a1 += fc3_w[128 + j] * f2;
            c0 += fc3_w[j] * f2b;      c1 += fc3_w[128 + j] * f2b;
        }
        sAC[0] = a0; sAC[1] = a1;
        sAC[2] = c0 + fc3_b[0]; sAC[3] = c1 + fc3_b[1];
    }
    __syncthreads();

    int warp = tid >> 5, lane = tid & 31;
    int b = blockIdx.x * 8 + warp;
    const float* p3 = g_buf3 + (size_t)b * 2304;
    const float* w1 = fc1_w + 2304;
    float s = 0.f;
    for (int i = lane; i < 2304; i += 32) s += p3[i] * w1[i];
    #pragma unroll
    for (int o = 16; o; o >>= 1) s += __shfl_xor_sync(0xffffffffu, s, o);
    if (lane == 0) {
        s += fc1_b[1];
        float q = cosf(s) * cosf(qp[1]);
        float l0 = q * sAC[0] + sAC[2];
        float l1 = q * sAC[1] + sAC[3];
        float mx = fmaxf(l0, l1);
        float lse = mx + logf(expf(l0 - mx) + expf(l1 - mx));
        out[(size_t)b * 2]     = l0 - lse;
        out[(size_t)b * 2 + 1] = l1 - lse;
    }
}

// ---------------------------------------------------------------------------
extern "C" void kernel_launch(void* const* d_in, const int* in_sizes, int n_in,
                              void* d_out, int out_size)
{
    const float* x    = (const float*)d_in[0];
    const float* c1w  = (const float*)d_in[1];
    const float* c1b  = (const float*)d_in[2];
    const float* c2w  = (const float*)d_in[3];
    const float* c2b  = (const float*)d_in[4];
    const float* c3w  = (const float*)d_in[5];
    const float* c3b  = (const float*)d_in[6];
    const float* bn1g = (const float*)d_in[7];
    const float* bn1b = (const float*)d_in[8];
    const float* bn1m = (const float*)d_in[9];
    const float* bn1v = (const float*)d_in[10];
    const float* bn2g = (const float*)d_in[11];
    const float* bn2b = (const float*)d_in[12];
    const float* bn2m = (const float*)d_in[13];
    const float* bn2v = (const float*)d_in[14];
    const float* bn3g = (const float*)d_in[15];
    const float* bn3b = (const float*)d_in[16];
    const float* bn3m = (const float*)d_in[17];
    const float* bn3v = (const float*)d_in[18];
    const float* fc1w = (const float*)d_in[19];
    const float* fc1b = (const float*)d_in[20];
    const float* qpar = (const float*)d_in[21];
    const float* fc2w = (const float*)d_in[22];
    const float* fc2b = (const float*)d_in[23];
    const float* fc3w = (const float*)d_in[24];
    const float* fc3b = (const float*)d_in[25];
    float* out = (float*)d_out;

    cudaFuncSetAttribute(conv2_mma, cudaFuncAttributeMaxDynamicSharedMemorySize, C2_SMEM);
    cudaFuncSetAttribute(conv3_mma, cudaFuncAttributeMaxDynamicSharedMemorySize, C3_SMEM);

    conv1_kernel<<<B_IMG, 256>>>(x, c1w, c1b, bn1g, bn1b, bn1m, bn1v);
    wtrans_kernel<<<(18 * 256 * 64 + 255) / 256, 256>>>(c2w, c3w);
    conv2_mma<<<592, 512, C2_SMEM>>>(c2b, bn2g, bn2b, bn2m, bn2v);
    conv3_mma<<<dim3(B_IMG / 4, 2), 512, C3_SMEM>>>(c3b, bn3g, bn3b, bn3m, bn3v);
    tail_kernel<<<B_IMG / 8, 256>>>(fc1w, fc1b, qpar, fc2w, fc2b, fc3w, fc3b, out);
}

// round 4
// speedup vs baseline: 10.7019x; 1.9134x over previous
#include <cuda_runtime.h>
#include <cuda_bf16.h>
#include <math.h>
#include <stddef.h>
#include <stdint.h>

#define B_IMG 8192
#define PLANE_ELEMS (((size_t)B_IMG * 64 + 64) * 64)

// Persistent device buffers (module-load zero-init; never-written pads stay 0)
__device__ __nv_bfloat16 g_act1[((size_t)B_IMG * 256 + 64) * 64]; // [B*16*16+pad][64]
__device__ __nv_bfloat16 g_act2[2 * PLANE_ELEMS];                 // 2 planes [B*8*8+pad][64]
__device__ float         g_buf3[(size_t)B_IMG * 2304];            // [B][256*3*3]
__device__ __nv_bfloat16 g_w2T[9 * 128 * 64];                     // [s][oc][ic]
__device__ __nv_bfloat16 g_w3T[18 * 256 * 64];                    // [s9*2+h][oc][ic_local]

__device__ __forceinline__ uint32_t smem_u32(const void* p) {
    uint32_t a;
    asm("{ .reg .u64 t; cvta.to.shared.u64 t, %1; cvt.u32.u64 %0, t; }" : "=r"(a) : "l"(p));
    return a;
}

#define LDSM_X4(R, addr) \
    asm volatile("ldmatrix.sync.aligned.m8n8.x4.shared.b16 {%0,%1,%2,%3}, [%4];" \
                 : "=r"((R)[0]), "=r"((R)[1]), "=r"((R)[2]), "=r"((R)[3]) : "r"(addr))

#define MMA16816(d, a, b0, b1) \
    asm volatile("mma.sync.aligned.m16n8k16.row.col.f32.bf16.bf16.f32 " \
                 "{%0,%1,%2,%3}, {%4,%5,%6,%7}, {%8,%9}, {%0,%1,%2,%3};" \
                 : "+f"((d)[0]), "+f"((d)[1]), "+f"((d)[2]), "+f"((d)[3]) \
                 : "r"((a)[0]), "r"((a)[1]), "r"((a)[2]), "r"((a)[3]), "r"(b0), "r"(b1))

#define CP16(sm, gp) \
    asm volatile("cp.async.cg.shared.global [%0], [%1], 16;" :: "r"((uint32_t)(sm)), "l"(gp))
#define CP_COMMIT() asm volatile("cp.async.commit_group;" ::: "memory")
#define CP_WAIT0()  asm volatile("cp.async.wait_group 0;" ::: "memory")
#define CP_WAIT1()  asm volatile("cp.async.wait_group 1;" ::: "memory")
#define BAR_GRP(id) asm volatile("bar.sync %0, %1;" :: "r"(id), "r"(128) : "memory")

// ---------------------------------------------------------------------------
// conv1 (FFMA): 1->64, 3x3 SAME, BN+ReLU+pool -> bf16 padded NHWC act1 (16x16)
// Interior-only writes (borders stay module-load zero).
// ---------------------------------------------------------------------------
__global__ __launch_bounds__(256) void conv1_kernel(
    const float* __restrict__ x, const float* __restrict__ w, const float* __restrict__ cb,
    const float* __restrict__ g, const float* __restrict__ bb,
    const float* __restrict__ m, const float* __restrict__ v)
{
    __shared__ float sIn[30 * 30];
    __shared__ float sW[64 * 9];
    __shared__ float sA[64];
    __shared__ float sB[64];
    int b = blockIdx.x, tid = threadIdx.x;

    for (int i = tid; i < 900; i += 256) sIn[i] = 0.f;
    for (int i = tid; i < 576; i += 256) sW[i] = w[i];
    if (tid < 64) {
        float a = g[tid] * rsqrtf(v[tid] + 1e-5f);
        sA[tid] = a;
        sB[tid] = (cb[tid] - m[tid]) * a + bb[tid];
    }
    __syncthreads();
    const float* xb = x + (size_t)b * 784;
    for (int i = tid; i < 784; i += 256) {
        int r = i / 28, c = i % 28;
        sIn[(r + 1) * 30 + c + 1] = xb[i];
    }
    __syncthreads();

    int oc = tid & 63;
    const float* wp = sW + oc * 9;
    float w0 = wp[0], w1 = wp[1], w2 = wp[2], w3 = wp[3], w4 = wp[4],
          w5 = wp[5], w6 = wp[6], w7 = wp[7], w8 = wp[8];
    float alpha = sA[oc], beta = sB[oc];
    __nv_bfloat16* ob = g_act1 + (size_t)b * 256 * 64;

    for (int idx = tid; idx < 196 * 64; idx += 256) {
        int pos = idx >> 6;                 // 0..195 pooled position
        int py = pos / 14, px = pos % 14;
        float best = -3.0e38f;
        #pragma unroll
        for (int dy = 0; dy < 2; dy++)
            #pragma unroll
            for (int dx = 0; dx < 2; dx++) {
                const float* pi = sIn + (2 * py + dy) * 30 + 2 * px + dx;
                float acc = w0 * pi[0] + w1 * pi[1] + w2 * pi[2]
                          + w3 * pi[30] + w4 * pi[31] + w5 * pi[32]
                          + w6 * pi[60] + w7 * pi[61] + w8 * pi[62];
                best = fmaxf(best, alpha * acc + beta);
            }
        ob[((py + 1) * 16 + px + 1) * 64 + oc] = __float2bfloat16(fmaxf(best, 0.f));
    }
}

// ---------------------------------------------------------------------------
// Weight transform: OIHW fp32 -> offset-major bf16 GEMM A-tiles
// ---------------------------------------------------------------------------
__global__ __launch_bounds__(256) void wtrans_kernel(
    const float* __restrict__ w2, const float* __restrict__ w3)
{
    int i = blockIdx.x * 256 + threadIdx.x;
    if (i < 9 * 128 * 64) {
        int ic = i & 63, t = i >> 6;
        int oc = t & 127, s = t >> 7;
        g_w2T[i] = __float2bfloat16(w2[(oc * 64 + ic) * 9 + s]);
    }
    if (i < 18 * 256 * 64) {
        int icl = i & 63, t = i >> 6;
        int oc = t & 255, gi = t >> 8;      // gi = s9*2 + h
        int h = gi & 1, s9 = gi >> 1;
        g_w3T[i] = __float2bfloat16(w3[(oc * 128 + h * 64 + icl) * 9 + s9]);
    }
}

// ---------------------------------------------------------------------------
// conv2 HMMA (persistent): D[128oc x 256pos] per image, 9 shifts x K=64.
// Weights resident; next image's act tile prefetched via cp.async during the
// epilogue. Epilogue: BN+ReLU+2x2pool -> bf16 act2.
// ---------------------------------------------------------------------------
#define C2_SW_BYTES (9 * 128 * 144)              // 165888
#define C2_SB_OFF   C2_SW_BYTES
#define C2_SMEM     (C2_SW_BYTES + 264 * 144)    // 203904

__global__ __launch_bounds__(512, 1) void conv2_mma(
    const float* __restrict__ cb, const float* __restrict__ g,
    const float* __restrict__ bb, const float* __restrict__ m,
    const float* __restrict__ v)
{
    extern __shared__ char dsm[];
    uint32_t sb = smem_u32(dsm);
    int tid = threadIdx.x;
    int lane = tid & 31, warp = tid >> 5;
    int wm = warp & 3, wn = warp >> 2;
    int t4 = lane & 3, trow = lane >> 2;

    // Load all 9 weight tiles into pitched smem (once per CTA)
    for (int i = tid; i < 9216; i += 512) {
        uint4 val = ((const uint4*)g_w2T)[i];
        *(uint4*)(dsm + (i >> 3) * 144 + (i & 7) * 16) = val;
    }

    // BN affine per thread's 4 oc rows
    float al[2][2], be[2][2];
    #pragma unroll
    for (int i = 0; i < 2; i++)
        #pragma unroll
        for (int ro = 0; ro < 2; ro++) {
            int oc = wm * 32 + i * 16 + trow + ro * 8;
            float a = g[oc] * rsqrtf(v[oc] + 1e-5f);
            al[i][ro] = a;
            be[i][ro] = (cb[oc] - m[oc]) * a + bb[oc];
        }

    int npairs = (wn == 3) ? 2 : 4;

    // Prefetch first image's act tile
    int img0 = blockIdx.x;
    if (img0 < B_IMG) {
        const char* src = (const char*)(g_act1 + (size_t)img0 * 256 * 64);
        for (int i = tid; i < 2112; i += 512)
            CP16(sb + C2_SB_OFF + (i >> 3) * 144 + (i & 7) * 16, src + i * 16);
    }
    CP_COMMIT();
    __syncthreads();     // weights visible

    for (int img = img0; img < B_IMG; img += gridDim.x) {
        CP_WAIT0();
        __syncthreads();                    // act tile visible to all

        float acc[2][8][4];
        #pragma unroll
        for (int i = 0; i < 2; i++)
            #pragma unroll
            for (int j = 0; j < 8; j++)
                #pragma unroll
                for (int k = 0; k < 4; k++) acc[i][j][k] = 0.f;

        #pragma unroll 1
        for (int s = 0; s < 9; s++) {
            int shift = (s / 3) * 16 + (s % 3);
            uint32_t aB = sb + s * 18432 + (wm * 32) * 144;
            uint32_t bB = sb + C2_SB_OFF + (shift + wn * 64) * 144;
            #pragma unroll
            for (int kt = 0; kt < 4; kt++) {
                uint32_t a[2][4];
                #pragma unroll
                for (int i = 0; i < 2; i++) {
                    uint32_t addr = aB + (i * 16 + (lane & 15)) * 144 + ((lane >> 4) & 1) * 16 + kt * 32;
                    LDSM_X4(a[i], addr);
                }
                #pragma unroll
                for (int jp = 0; jp < 4; jp++) {
                    if (jp < npairs) {
                        uint32_t r[4];
                        uint32_t addr = bB + (jp * 16 + ((lane & 16) >> 1) + (lane & 7)) * 144
                                        + kt * 32 + ((lane >> 3) & 1) * 16;
                        LDSM_X4(r, addr);
                        #pragma unroll
                        for (int i = 0; i < 2; i++) {
                            MMA16816(acc[i][2 * jp],     a[i], r[0], r[1]);
                            MMA16816(acc[i][2 * jp + 1], a[i], r[2], r[3]);
                        }
                    }
                }
            }
        }
        __syncthreads();                    // all warps done reading act tile

        // Prefetch next image's act tile; drains during epilogue
        int nxt = img + gridDim.x;
        if (nxt < B_IMG) {
            const char* src = (const char*)(g_act1 + (size_t)nxt * 256 * 64);
            for (int i = tid; i < 2112; i += 512)
                CP16(sb + C2_SB_OFF + (i >> 3) * 144 + (i & 7) * 16, src + i * 16);
        }
        CP_COMMIT();

        // Epilogue: BN + ReLU + 2x2 pool -> act2 interior
        #pragma unroll
        for (int i = 0; i < 2; i++)
            #pragma unroll
            for (int jj = 0; jj < 4; jj++) {
                int j = (jj < 2) ? jj : jj + 2;   // {0,1,4,5}
                int n0 = wn * 64 + j * 8 + 2 * t4;
                int p = n0 + 17;
                int r = p >> 4, c = p & 15;
                if ((r & 1) && r < 15 && (c & 1) && c < 15) {
                    #pragma unroll
                    for (int ro = 0; ro < 2; ro++) {
                        float a = al[i][ro], bt = be[i][ro];
                        float v0 = a * acc[i][j][2 * ro] + bt;
                        float v1 = a * acc[i][j][2 * ro + 1] + bt;
                        float v2 = a * acc[i][j + 2][2 * ro] + bt;
                        float v3 = a * acc[i][j + 2][2 * ro + 1] + bt;
                        float mx = fmaxf(fmaxf(fmaxf(v0, v1), fmaxf(v2, v3)), 0.f);
                        int oc = wm * 32 + i * 16 + trow + ro * 8;
                        int py = (r - 1) >> 1, px = (c - 1) >> 1;
                        g_act2[(size_t)(oc >> 6) * PLANE_ELEMS +
                               ((size_t)img * 64 + (py + 1) * 8 + px + 1) * 64 + (oc & 63)]
                            = __float2bfloat16(mx);
                    }
                }
            }
    }
}

// ---------------------------------------------------------------------------
// conv3 HMMA: per CTA 4 images x 128 oc. 9 stages (K=128 each = both planes).
// B planes resident; A slices are wm-group private with a 3-deep cp.async
// ring + named barriers -> no CTA-wide sync in the mainloop.
// Epilogue: BN+ReLU+pool(6x6->3x3) -> fp32 g_buf3.
// ---------------------------------------------------------------------------
#define C3_SB_BYTES (274 * 144)                   // 39456 per plane
#define C3_A_OFF    (2 * C3_SB_BYTES)             // 78912
#define C3_A_STAGE  9216                          // 2 halves x 32 rows x 144B
#define C3_SMEM     (C3_A_OFF + 4 * 3 * C3_A_STAGE) // 189504

__global__ __launch_bounds__(512, 1) void conv3_mma(
    const float* __restrict__ cb, const float* __restrict__ g,
    const float* __restrict__ bb, const float* __restrict__ m,
    const float* __restrict__ v)
{
    extern __shared__ char dsm[];
    uint32_t sb = smem_u32(dsm);
    int tid = threadIdx.x;
    int lane = tid & 31, warp = tid >> 5;
    int wm = warp & 3, wn = warp >> 2;
    int t4 = lane & 3, trow = lane >> 2;
    int grp = blockIdx.x, half = blockIdx.y;
    int gi = wn * 32 + lane;                      // 0..127 within wm-group

    // A-slice prefetch for stage s into ring buffer s%3 (wm-group private)
    auto prefA = [&](int s) {
        uint32_t dst0 = sb + C3_A_OFF + (uint32_t)(wm * 3 + (s % 3)) * C3_A_STAGE;
        #pragma unroll
        for (int u = 0; u < 4; u++) {
            int idx = gi + u * 128;               // 0..511
            int h = idx >> 8, rem = idx & 255;
            int row = rem >> 3, q = rem & 7;
            uint32_t dst = dst0 + h * 4608 + row * 144 + q * 16;
            const char* src = (const char*)g_w3T +
                ((((size_t)(s * 2 + h) * 256 + half * 128 + wm * 32 + row) * 64) + q * 8) * 2;
            CP16(dst, src);
        }
    };

    // B: both planes, 274 rows each, via cp.async (group G0 together with A0)
    {
        const char* p0 = (const char*)(g_act2 + (size_t)grp * 256 * 64);
        const char* p1 = (const char*)(g_act2 + PLANE_ELEMS + (size_t)grp * 256 * 64);
        for (int i = tid; i < 2192; i += 512) {
            uint32_t d = sb + (i >> 3) * 144 + (i & 7) * 16;
            CP16(d, p0 + i * 16);
            CP16(d + C3_SB_BYTES, p1 + i * 16);
        }
    }
    prefA(0);
    CP_COMMIT();            // G0 = B + A0
    prefA(1);
    CP_COMMIT();            // G1 = A1
    CP_WAIT1();             // G0 complete
    __syncthreads();        // B + A0 visible to all

    float acc[2][8][4];
    #pragma unroll
    for (int i = 0; i < 2; i++)
        #pragma unroll
        for (int j = 0; j < 8; j++)
            #pragma unroll
            for (int k = 0; k < 4; k++) acc[i][j][k] = 0.f;

    #pragma unroll 1
    for (int s = 0; s < 9; s++) {
        if (s + 2 < 9) prefA(s + 2);
        CP_COMMIT();                               // uniform group numbering

        int shift = (s / 3) * 8 + (s % 3);
        uint32_t aS = sb + C3_A_OFF + (uint32_t)(wm * 3 + (s % 3)) * C3_A_STAGE;
        #pragma unroll
        for (int h = 0; h < 2; h++) {
            uint32_t aB = aS + h * 4608;
            uint32_t bB = sb + h * C3_SB_BYTES + (shift + wn * 64) * 144;
            #pragma unroll
            for (int kt = 0; kt < 4; kt++) {
                uint32_t a[2][4];
                #pragma unroll
                for (int i = 0; i < 2; i++) {
                    uint32_t addr = aB + (i * 16 + (lane & 15)) * 144 + ((lane >> 4) & 1) * 16 + kt * 32;
                    LDSM_X4(a[i], addr);
                }
                #pragma unroll
                for (int jp = 0; jp < 4; jp++) {
                    uint32_t r[4];
                    uint32_t addr = bB + (jp * 16 + ((lane & 16) >> 1) + (lane & 7)) * 144
                                    + kt * 32 + ((lane >> 3) & 1) * 16;
                    LDSM_X4(r, addr);
                    #pragma unroll
                    for (int i = 0; i < 2; i++) {
                        MMA16816(acc[i][2 * jp],     a[i], r[0], r[1]);
                        MMA16816(acc[i][2 * jp + 1], a[i], r[2], r[3]);
                    }
                }
            }
        }
        CP_WAIT1();                                // A(s+1) complete
        BAR_GRP(1 + wm);                           // group-local: visible + ring safe
    }

    // Epilogue: BN + ReLU + pool -> g_buf3. Warp n-col wn = local image.
    #pragma unroll
    for (int i = 0; i < 2; i++)
        #pragma unroll
        for (int jh = 0; jh < 3; jh++) {
            int j = 2 * jh;                 // {0,2,4}
            if (t4 < 3) {
                #pragma unroll
                for (int ro = 0; ro < 2; ro++) {
                    int ch = half * 128 + wm * 32 + i * 16 + trow + ro * 8;
                    float a = g[ch] * rsqrtf(v[ch] + 1e-5f);
                    float bt = (cb[ch] - m[ch]) * a + bb[ch];
                    float v0 = a * acc[i][j][2 * ro] + bt;
                    float v1 = a * acc[i][j][2 * ro + 1] + bt;
                    float v2 = a * acc[i][j + 1][2 * ro] + bt;
                    float v3 = a * acc[i][j + 1][2 * ro + 1] + bt;
                    float mx = fmaxf(fmaxf(fmaxf(v0, v1), fmaxf(v2, v3)), 0.f);
                    g_buf3[(size_t)(grp * 4 + wn) * 2304 + ch * 9 + jh * 3 + t4] = mx;
                }
            }
        }
}

// ---------------------------------------------------------------------------
// Tail: analytic quantum collapse + fc chain + log_softmax. 1 warp / image.
// ---------------------------------------------------------------------------
__global__ __launch_bounds__(256) void tail_kernel(
    const float* __restrict__ fc1_w, const float* __restrict__ fc1_b,
    const float* __restrict__ qp,
    const float* __restrict__ fc2_w, const float* __restrict__ fc2_b,
    const float* __restrict__ fc3_w, const float* __restrict__ fc3_b,
    float* __restrict__ out)
{
    __shared__ float sAC[4];
    int tid = threadIdx.x;
    if (tid == 0) {
        float a0 = 0.f, a1 = 0.f, c0 = 0.f, c1 = 0.f;
        for (int j = 0; j < 128; j++) {
            float f2 = fc2_w[j], f2b = fc2_b[j];
            a0 += fc3_w[j] * f2;       a1 += fc3_w[128 + j] * f2;
            c0 += fc3_w[j] * f2b;      c1 += fc3_w[128 + j] * f2b;
        }
        sAC[0] = a0; sAC[1] = a1;
        sAC[2] = c0 + fc3_b[0]; sAC[3] = c1 + fc3_b[1];
    }
    __syncthreads();

    int warp = tid >> 5, lane = tid & 31;
    int b = blockIdx.x * 8 + warp;
    const float* p3 = g_buf3 + (size_t)b * 2304;
    const float* w1 = fc1_w + 2304;
    float s = 0.f;
    for (int i = lane; i < 2304; i += 32) s += p3[i] * w1[i];
    #pragma unroll
    for (int o = 16; o; o >>= 1) s += __shfl_xor_sync(0xffffffffu, s, o);
    if (lane == 0) {
        s += fc1_b[1];
        float q = cosf(s) * cosf(qp[1]);
        float l0 = q * sAC[0] + sAC[2];
        float l1 = q * sAC[1] + sAC[3];
        float mx = fmaxf(l0, l1);
        float lse = mx + logf(expf(l0 - mx) + expf(l1 - mx));
        out[(size_t)b * 2]     = l0 - lse;
        out[(size_t)b * 2 + 1] = l1 - lse;
    }
}

// ---------------------------------------------------------------------------
extern "C" void kernel_launch(void* const* d_in, const int* in_sizes, int n_in,
                              void* d_out, int out_size)
{
    const float* x    = (const float*)d_in[0];
    const float* c1w  = (const float*)d_in[1];
    const float* c1b  = (const float*)d_in[2];
    const float* c2w  = (const float*)d_in[3];
    const float* c2b  = (const float*)d_in[4];
    const float* c3w  = (const float*)d_in[5];
    const float* c3b  = (const float*)d_in[6];
    const float* bn1g = (const float*)d_in[7];
    const float* bn1b = (const float*)d_in[8];
    const float* bn1m = (const float*)d_in[9];
    const float* bn1v = (const float*)d_in[10];
    const float* bn2g = (const float*)d_in[11];
    const float* bn2b = (const float*)d_in[12];
    const float* bn2m = (const float*)d_in[13];
    const float* bn2v = (const float*)d_in[14];
    const float* bn3g = (const float*)d_in[15];
    const float* bn3b = (const float*)d_in[16];
    const float* bn3m = (const float*)d_in[17];
    const float* bn3v = (const float*)d_in[18];
    const float* fc1w = (const float*)d_in[19];
    const float* fc1b = (const float*)d_in[20];
    const float* qpar = (const float*)d_in[21];
    const float* fc2w = (const float*)d_in[22];
    const float* fc2b = (const float*)d_in[23];
    const float* fc3w = (const float*)d_in[24];
    const float* fc3b = (const float*)d_in[25];
    float* out = (float*)d_out;

    cudaFuncSetAttribute(conv2_mma, cudaFuncAttributeMaxDynamicSharedMemorySize, C2_SMEM);
    cudaFuncSetAttribute(conv3_mma, cudaFuncAttributeMaxDynamicSharedMemorySize, C3_SMEM);

    conv1_kernel<<<B_IMG, 256>>>(x, c1w, c1b, bn1g, bn1b, bn1m, bn1v);
    wtrans_kernel<<<(18 * 256 * 64 + 255) / 256, 256>>>(c2w, c3w);
    conv2_mma<<<592, 512, C2_SMEM>>>(c2b, bn2g, bn2b, bn2m, bn2v);
    conv3_mma<<<dim3(B_IMG / 4, 2), 512, C3_SMEM>>>(c3b, bn3g, bn3b, bn3m, bn3v);
    tail_kernel<<<B_IMG / 8, 256>>>(fc1w, fc1b, qpar, fc2w, fc2b, fc3w, fc3b, out);
}

// round 5
// speedup vs baseline: 10.8511x; 1.0139x over previous
#include <cuda_runtime.h>
#include <cuda_bf16.h>
#include <math.h>
#include <stddef.h>
#include <stdint.h>

#define B_IMG 8192
#define PLANE_ELEMS (((size_t)B_IMG * 64 + 64) * 64)

// Persistent device buffers (module-load zero-init; never-written pads stay 0)
__device__ __nv_bfloat16 g_act1[((size_t)B_IMG * 256 + 64) * 64]; // [B*16*16+pad][64]
__device__ __nv_bfloat16 g_act2[2 * PLANE_ELEMS];                 // 2 planes [B*8*8+pad][64]
__device__ float         g_buf3[(size_t)B_IMG * 2304];            // [B][256*3*3]
__device__ __nv_bfloat16 g_w2T[9 * 128 * 64];                     // [s][oc][ic]
__device__ __nv_bfloat16 g_w3T[18 * 256 * 64];                    // [s9*2+h][oc][ic_local]

__device__ __forceinline__ uint32_t smem_u32(const void* p) {
    uint32_t a;
    asm("{ .reg .u64 t; cvta.to.shared.u64 t, %1; cvt.u32.u64 %0, t; }" : "=r"(a) : "l"(p));
    return a;
}

#define LDSM_X4(R, addr) \
    asm volatile("ldmatrix.sync.aligned.m8n8.x4.shared.b16 {%0,%1,%2,%3}, [%4];" \
                 : "=r"((R)[0]), "=r"((R)[1]), "=r"((R)[2]), "=r"((R)[3]) : "r"(addr))

#define MMA16816(d, a, b0, b1) \
    asm volatile("mma.sync.aligned.m16n8k16.row.col.f32.bf16.bf16.f32 " \
                 "{%0,%1,%2,%3}, {%4,%5,%6,%7}, {%8,%9}, {%0,%1,%2,%3};" \
                 : "+f"((d)[0]), "+f"((d)[1]), "+f"((d)[2]), "+f"((d)[3]) \
                 : "r"((a)[0]), "r"((a)[1]), "r"((a)[2]), "r"((a)[3]), "r"(b0), "r"(b1))

#define CP16(sm, gp) \
    asm volatile("cp.async.cg.shared.global [%0], [%1], 16;" :: "r"((uint32_t)(sm)), "l"(gp))
#define CP_COMMIT() asm volatile("cp.async.commit_group;" ::: "memory")
#define CP_WAIT0()  asm volatile("cp.async.wait_group 0;" ::: "memory")
#define CP_WAIT1()  asm volatile("cp.async.wait_group 1;" ::: "memory")
#define BAR_GRP(id, n) asm volatile("bar.sync %0, %1;" :: "r"(id), "r"(n) : "memory")

// ---------------------------------------------------------------------------
// conv1 (FFMA): 1->64, 3x3 SAME, BN+ReLU+pool -> bf16 padded NHWC act1 (16x16)
// ---------------------------------------------------------------------------
__global__ __launch_bounds__(256) void conv1_kernel(
    const float* __restrict__ x, const float* __restrict__ w, const float* __restrict__ cb,
    const float* __restrict__ g, const float* __restrict__ bb,
    const float* __restrict__ m, const float* __restrict__ v)
{
    __shared__ float sIn[30 * 30];
    __shared__ float sW[64 * 9];
    __shared__ float sA[64];
    __shared__ float sB[64];
    int b = blockIdx.x, tid = threadIdx.x;

    for (int i = tid; i < 900; i += 256) sIn[i] = 0.f;
    for (int i = tid; i < 576; i += 256) sW[i] = w[i];
    if (tid < 64) {
        float a = g[tid] * rsqrtf(v[tid] + 1e-5f);
        sA[tid] = a;
        sB[tid] = (cb[tid] - m[tid]) * a + bb[tid];
    }
    __syncthreads();
    const float* xb = x + (size_t)b * 784;
    for (int i = tid; i < 784; i += 256) {
        int r = i / 28, c = i % 28;
        sIn[(r + 1) * 30 + c + 1] = xb[i];
    }
    __syncthreads();

    int oc = tid & 63;
    const float* wp = sW + oc * 9;
    float w0 = wp[0], w1 = wp[1], w2 = wp[2], w3 = wp[3], w4 = wp[4],
          w5 = wp[5], w6 = wp[6], w7 = wp[7], w8 = wp[8];
    float alpha = sA[oc], beta = sB[oc];
    __nv_bfloat16* ob = g_act1 + (size_t)b * 256 * 64;

    for (int idx = tid; idx < 196 * 64; idx += 256) {
        int pos = idx >> 6;
        int py = pos / 14, px = pos % 14;
        float best = -3.0e38f;
        #pragma unroll
        for (int dy = 0; dy < 2; dy++)
            #pragma unroll
            for (int dx = 0; dx < 2; dx++) {
                const float* pi = sIn + (2 * py + dy) * 30 + 2 * px + dx;
                float acc = w0 * pi[0] + w1 * pi[1] + w2 * pi[2]
                          + w3 * pi[30] + w4 * pi[31] + w5 * pi[32]
                          + w6 * pi[60] + w7 * pi[61] + w8 * pi[62];
                best = fmaxf(best, alpha * acc + beta);
            }
        ob[((py + 1) * 16 + px + 1) * 64 + oc] = __float2bfloat16(fmaxf(best, 0.f));
    }
}

// ---------------------------------------------------------------------------
// Weight transform: OIHW fp32 -> offset-major bf16 GEMM A-tiles
// ---------------------------------------------------------------------------
__global__ __launch_bounds__(256) void wtrans_kernel(
    const float* __restrict__ w2, const float* __restrict__ w3)
{
    int i = blockIdx.x * 256 + threadIdx.x;
    if (i < 9 * 128 * 64) {
        int ic = i & 63, t = i >> 6;
        int oc = t & 127, s = t >> 7;
        g_w2T[i] = __float2bfloat16(w2[(oc * 64 + ic) * 9 + s]);
    }
    if (i < 18 * 256 * 64) {
        int icl = i & 63, t = i >> 6;
        int oc = t & 255, gi = t >> 8;      // gi = s9*2 + h
        int h = gi & 1, s9 = gi >> 1;
        g_w3T[i] = __float2bfloat16(w3[(oc * 128 + h * 64 + icl) * 9 + s9]);
    }
}

// ---------------------------------------------------------------------------
// conv2 HMMA (persistent): D[128oc x 256pos] per image, 9 shifts x K=64.
// Weights resident; next image's act tile prefetched via cp.async during the
// epilogue. Epilogue: BN+ReLU+2x2pool -> bf16 act2.
// ---------------------------------------------------------------------------
#define C2_SW_BYTES (9 * 128 * 144)              // 165888
#define C2_SB_OFF   C2_SW_BYTES
#define C2_SMEM     (C2_SW_BYTES + 264 * 144)    // 203904

__global__ __launch_bounds__(512, 1) void conv2_mma(
    const float* __restrict__ cb, const float* __restrict__ g,
    const float* __restrict__ bb, const float* __restrict__ m,
    const float* __restrict__ v)
{
    extern __shared__ char dsm[];
    uint32_t sb = smem_u32(dsm);
    int tid = threadIdx.x;
    int lane = tid & 31, warp = tid >> 5;
    int wm = warp & 3, wn = warp >> 2;
    int t4 = lane & 3, trow = lane >> 2;

    for (int i = tid; i < 9216; i += 512) {
        uint4 val = ((const uint4*)g_w2T)[i];
        *(uint4*)(dsm + (i >> 3) * 144 + (i & 7) * 16) = val;
    }

    float al[2][2], be[2][2];
    #pragma unroll
    for (int i = 0; i < 2; i++)
        #pragma unroll
        for (int ro = 0; ro < 2; ro++) {
            int oc = wm * 32 + i * 16 + trow + ro * 8;
            float a = g[oc] * rsqrtf(v[oc] + 1e-5f);
            al[i][ro] = a;
            be[i][ro] = (cb[oc] - m[oc]) * a + bb[oc];
        }

    int npairs = (wn == 3) ? 2 : 4;

    int img0 = blockIdx.x;
    if (img0 < B_IMG) {
        const char* src = (const char*)(g_act1 + (size_t)img0 * 256 * 64);
        for (int i = tid; i < 2112; i += 512)
            CP16(sb + C2_SB_OFF + (i >> 3) * 144 + (i & 7) * 16, src + i * 16);
    }
    CP_COMMIT();
    __syncthreads();

    for (int img = img0; img < B_IMG; img += gridDim.x) {
        CP_WAIT0();
        __syncthreads();

        float acc[2][8][4];
        #pragma unroll
        for (int i = 0; i < 2; i++)
            #pragma unroll
            for (int j = 0; j < 8; j++)
                #pragma unroll
                for (int k = 0; k < 4; k++) acc[i][j][k] = 0.f;

        #pragma unroll 1
        for (int s = 0; s < 9; s++) {
            int shift = (s / 3) * 16 + (s % 3);
            uint32_t aB = sb + s * 18432 + (wm * 32) * 144;
            uint32_t bB = sb + C2_SB_OFF + (shift + wn * 64) * 144;
            #pragma unroll
            for (int kt = 0; kt < 4; kt++) {
                uint32_t a[2][4];
                #pragma unroll
                for (int i = 0; i < 2; i++) {
                    uint32_t addr = aB + (i * 16 + (lane & 15)) * 144 + ((lane >> 4) & 1) * 16 + kt * 32;
                    LDSM_X4(a[i], addr);
                }
                #pragma unroll
                for (int jp = 0; jp < 4; jp++) {
                    if (jp < npairs) {
                        uint32_t r[4];
                        uint32_t addr = bB + (jp * 16 + ((lane & 16) >> 1) + (lane & 7)) * 144
                                        + kt * 32 + ((lane >> 3) & 1) * 16;
                        LDSM_X4(r, addr);
                        #pragma unroll
                        for (int i = 0; i < 2; i++) {
                            MMA16816(acc[i][2 * jp],     a[i], r[0], r[1]);
                            MMA16816(acc[i][2 * jp + 1], a[i], r[2], r[3]);
                        }
                    }
                }
            }
        }
        __syncthreads();

        int nxt = img + gridDim.x;
        if (nxt < B_IMG) {
            const char* src = (const char*)(g_act1 + (size_t)nxt * 256 * 64);
            for (int i = tid; i < 2112; i += 512)
                CP16(sb + C2_SB_OFF + (i >> 3) * 144 + (i & 7) * 16, src + i * 16);
        }
        CP_COMMIT();

        #pragma unroll
        for (int i = 0; i < 2; i++)
            #pragma unroll
            for (int jj = 0; jj < 4; jj++) {
                int j = (jj < 2) ? jj : jj + 2;   // {0,1,4,5}
                int n0 = wn * 64 + j * 8 + 2 * t4;
                int p = n0 + 17;
                int r = p >> 4, c = p & 15;
                if ((r & 1) && r < 15 && (c & 1) && c < 15) {
                    #pragma unroll
                    for (int ro = 0; ro < 2; ro++) {
                        float a = al[i][ro], bt = be[i][ro];
                        float v0 = a * acc[i][j][2 * ro] + bt;
                        float v1 = a * acc[i][j][2 * ro + 1] + bt;
                        float v2 = a * acc[i][j + 2][2 * ro] + bt;
                        float v3 = a * acc[i][j + 2][2 * ro + 1] + bt;
                        float mx = fmaxf(fmaxf(fmaxf(v0, v1), fmaxf(v2, v3)), 0.f);
                        int oc = wm * 32 + i * 16 + trow + ro * 8;
                        int py = (r - 1) >> 1, px = (c - 1) >> 1;
                        g_act2[(size_t)(oc >> 6) * PLANE_ELEMS +
                               ((size_t)img * 64 + (py + 1) * 8 + px + 1) * 64 + (oc & 63)]
                            = __float2bfloat16(mx);
                    }
                }
            }
    }
}

// ---------------------------------------------------------------------------
// conv3 HMMA v2: 256 threads, 2 images x 128 oc per CTA, 2 CTAs/SM.
// 18 (s9,h) stages; A slices stream via wm-group-private 3-deep cp.async ring
// with 64-thread named barriers. Dead n8-tiles 6,7 skipped (jp 0..2 only).
// Epilogue: BN+ReLU+pool(6x6->3x3) -> fp32 g_buf3.
// ---------------------------------------------------------------------------
#define C3_B_WIN   9504                           // 66 rows * 144B
#define C3_A_OFF   (4 * C3_B_WIN)                 // 38016
#define C3_A_STAGE 4608                           // 32 rows * 144B
#define C3_SMEM    (C3_A_OFF + 4 * 3 * C3_A_STAGE) // 93312

__global__ __launch_bounds__(256, 2) void conv3_mma(
    const float* __restrict__ cb, const float* __restrict__ g,
    const float* __restrict__ bb, const float* __restrict__ m,
    const float* __restrict__ v)
{
    extern __shared__ char dsm[];
    uint32_t sb = smem_u32(dsm);
    int tid = threadIdx.x;
    int lane = tid & 31, warp = tid >> 5;
    int wm = warp & 3, wn = warp >> 2;            // wn = local image (0/1)
    int t4 = lane & 3, trow = lane >> 2;
    int grp2 = blockIdx.x, half = blockIdx.y;
    int gi = wn * 32 + lane;                      // 0..63 within wm-group

    // A-slice prefetch for stage st into ring slot st%3 (wm-group private)
    auto prefA = [&](int st) {
        uint32_t dst0 = sb + C3_A_OFF + (uint32_t)(wm * 3 + (st % 3)) * C3_A_STAGE;
        #pragma unroll
        for (int u = 0; u < 4; u++) {
            int idx = gi + u * 64;                // 0..255
            int row = idx >> 3, q = idx & 7;
            const char* src = (const char*)g_w3T +
                (((size_t)st * 256 + half * 128 + wm * 32 + row) * 64 + q * 8) * 2;
            CP16(dst0 + row * 144 + q * 16, src);
        }
    };

    // B: 4 windows (2 images x 2 planes) of 66 rows each
    for (int i = tid; i < 2112; i += 256) {
        int w = i / 528, rem = i - w * 528;
        int row = rem >> 3, q = rem & 7;
        int img = w >> 1, pl = w & 1;
        const char* src = (const char*)(g_act2 + (size_t)pl * PLANE_ELEMS +
                          ((size_t)(grp2 * 2 + img) * 64 + row) * 64 + q * 8);
        CP16(sb + (uint32_t)w * C3_B_WIN + row * 144 + q * 16, src);
    }
    prefA(0);
    CP_COMMIT();            // G0 = B + A0
    prefA(1);
    CP_COMMIT();            // G1 = A1
    CP_WAIT1();             // G0 complete
    __syncthreads();        // B + A0 visible to all

    float acc[2][6][4];
    #pragma unroll
    for (int i = 0; i < 2; i++)
        #pragma unroll
        for (int j = 0; j < 6; j++)
            #pragma unroll
            for (int k = 0; k < 4; k++) acc[i][j][k] = 0.f;

    #pragma unroll 1
    for (int st = 0; st < 18; st++) {
        if (st + 2 < 18) prefA(st + 2);
        CP_COMMIT();                               // uniform group numbering

        int s9 = st >> 1, h = st & 1;
        int shift = (s9 / 3) * 8 + (s9 % 3);
        uint32_t aB = sb + C3_A_OFF + (uint32_t)(wm * 3 + (st % 3)) * C3_A_STAGE;
        uint32_t bB = sb + (uint32_t)(wn * 2 + h) * C3_B_WIN + shift * 144;
        #pragma unroll
        for (int kt = 0; kt < 4; kt++) {
            uint32_t a[2][4];
            #pragma unroll
            for (int i = 0; i < 2; i++) {
                uint32_t addr = aB + (i * 16 + (lane & 15)) * 144 + ((lane >> 4) & 1) * 16 + kt * 32;
                LDSM_X4(a[i], addr);
            }
            #pragma unroll
            for (int jp = 0; jp < 3; jp++) {
                uint32_t r[4];
                uint32_t addr = bB + (jp * 16 + ((lane & 16) >> 1) + (lane & 7)) * 144
                                + kt * 32 + ((lane >> 3) & 1) * 16;
                LDSM_X4(r, addr);
                #pragma unroll
                for (int i = 0; i < 2; i++) {
                    MMA16816(acc[i][2 * jp],     a[i], r[0], r[1]);
                    MMA16816(acc[i][2 * jp + 1], a[i], r[2], r[3]);
                }
            }
        }
        CP_WAIT1();                                // A(st+1) complete
        BAR_GRP(1 + wm, 64);                       // group-local visibility + ring safety
    }

    // Epilogue: BN + ReLU + pool -> g_buf3
    int img = grp2 * 2 + wn;
    #pragma unroll
    for (int i = 0; i < 2; i++)
        #pragma unroll
        for (int ro = 0; ro < 2; ro++) {
            int ch = half * 128 + wm * 32 + i * 16 + trow + ro * 8;
            float a = g[ch] * rsqrtf(v[ch] + 1e-5f);
            float bt = (cb[ch] - m[ch]) * a + bb[ch];
            if (t4 < 3) {
                #pragma unroll
                for (int jh = 0; jh < 3; jh++) {
                    int j = 2 * jh;
                    float v0 = a * acc[i][j][2 * ro] + bt;
                    float v1 = a * acc[i][j][2 * ro + 1] + bt;
                    float v2 = a * acc[i][j + 1][2 * ro] + bt;
                    float v3 = a * acc[i][j + 1][2 * ro + 1] + bt;
                    float mx = fmaxf(fmaxf(fmaxf(v0, v1), fmaxf(v2, v3)), 0.f);
                    g_buf3[(size_t)img * 2304 + ch * 9 + jh * 3 + t4] = mx;
                }
            }
        }
}

// ---------------------------------------------------------------------------
// Tail: analytic quantum collapse + fc chain + log_softmax. 1 warp / image.
// ---------------------------------------------------------------------------
__global__ __launch_bounds__(256) void tail_kernel(
    const float* __restrict__ fc1_w, const float* __restrict__ fc1_b,
    const float* __restrict__ qp,
    const float* __restrict__ fc2_w, const float* __restrict__ fc2_b,
    const float* __restrict__ fc3_w, const float* __restrict__ fc3_b,
    float* __restrict__ out)
{
    __shared__ float sAC[4];
    int tid = threadIdx.x;
    if (tid == 0) {
        float a0 = 0.f, a1 = 0.f, c0 = 0.f, c1 = 0.f;
        for (int j = 0; j < 128; j++) {
            float f2 = fc2_w[j], f2b = fc2_b[j];
            a0 += fc3_w[j] * f2;       a1 += fc3_w[128 + j] * f2;
            c0 += fc3_w[j] * f2b;      c1 += fc3_w[128 + j] * f2b;
        }
        sAC[0] = a0; sAC[1] = a1;
        sAC[2] = c0 + fc3_b[0]; sAC[3] = c1 + fc3_b[1];
    }
    __syncthreads();

    int warp = tid >> 5, lane = tid & 31;
    int b = blockIdx.x * 8 + warp;
    const float* p3 = g_buf3 + (size_t)b * 2304;
    const float* w1 = fc1_w + 2304;
    float s = 0.f;
    for (int i = lane; i < 2304; i += 32) s += p3[i] * w1[i];
    #pragma unroll
    for (int o = 16; o; o >>= 1) s += __shfl_xor_sync(0xffffffffu, s, o);
    if (lane == 0) {
        s += fc1_b[1];
        float q = cosf(s) * cosf(qp[1]);
        float l0 = q * sAC[0] + sAC[2];
        float l1 = q * sAC[1] + sAC[3];
        float mx = fmaxf(l0, l1);
        float lse = mx + logf(expf(l0 - mx) + expf(l1 - mx));
        out[(size_t)b * 2]     = l0 - lse;
        out[(size_t)b * 2 + 1] = l1 - lse;
    }
}

// ---------------------------------------------------------------------------
extern "C" void kernel_launch(void* const* d_in, const int* in_sizes, int n_in,
                              void* d_out, int out_size)
{
    const float* x    = (const float*)d_in[0];
    const float* c1w  = (const float*)d_in[1];
    const float* c1b  = (const float*)d_in[2];
    const float* c2w  = (const float*)d_in[3];
    const float* c2b  = (const float*)d_in[4];
    const float* c3w  = (const float*)d_in[5];
    const float* c3b  = (const float*)d_in[6];
    const float* bn1g = (const float*)d_in[7];
    const float* bn1b = (const float*)d_in[8];
    const float* bn1m = (const float*)d_in[9];
    const float* bn1v = (const float*)d_in[10];
    const float* bn2g = (const float*)d_in[11];
    const float* bn2b = (const float*)d_in[12];
    const float* bn2m = (const float*)d_in[13];
    const float* bn2v = (const float*)d_in[14];
    const float* bn3g = (const float*)d_in[15];
    const float* bn3b = (const float*)d_in[16];
    const float* bn3m = (const float*)d_in[17];
    const float* bn3v = (const float*)d_in[18];
    const float* fc1w = (const float*)d_in[19];
    const float* fc1b = (const float*)d_in[20];
    const float* qpar = (const float*)d_in[21];
    const float* fc2w = (const float*)d_in[22];
    const float* fc2b = (const float*)d_in[23];
    const float* fc3w = (const float*)d_in[24];
    const float* fc3b = (const float*)d_in[25];
    float* out = (float*)d_out;

    cudaFuncSetAttribute(conv2_mma, cudaFuncAttributeMaxDynamicSharedMemorySize, C2_SMEM);
    cudaFuncSetAttribute(conv3_mma, cudaFuncAttributeMaxDynamicSharedMemorySize, C3_SMEM);

    conv1_kernel<<<B_IMG, 256>>>(x, c1w, c1b, bn1g, bn1b, bn1m, bn1v);
    wtrans_kernel<<<(18 * 256 * 64 + 255) / 256, 256>>>(c2w, c3w);
    conv2_mma<<<592, 512, C2_SMEM>>>(c2b, bn2g, bn2b, bn2m, bn2v);
    conv3_mma<<<dim3(B_IMG / 2, 2), 256, C3_SMEM>>>(c3b, bn3g, bn3b, bn3m, bn3v);
    tail_kernel<<<B_IMG / 8, 256>>>(fc1w, fc1b, qpar, fc2w, fc2b, fc3w, fc3b, out);
}